// round 10
// baseline (speedup 1.0000x reference)
#include <cuda_runtime.h>
#include <cuda_bf16.h>

#define NMAX 50000
#define EMAX 1700000

// ---------------- scratch ----------------
__device__ float g_h1[NMAX * 64];
__device__ float g_asrc1[NMAX * 8];
__device__ float g_adst1[NMAX * 8];
__device__ float g_h2in[NMAX * 64];
__device__ float g_h2[NMAX * 40];
__device__ float g_as2[NMAX];
__device__ float g_ad2[NMAX];
// CSR
__device__ int g_deg[NMAX];
__device__ int g_start[NMAX + 1];
__device__ int g_cursor[NMAX];
__device__ int g_csrc[EMAX];
__device__ int g_incl[64];
__device__ int g_flag[64];

__device__ __forceinline__ float leaky(float e) { return e >= 0.f ? e : 0.2f * e; }

// ---------------- SGEMM1: C[M,64] = A[M,512] @ B[512,64] + fused attn logits ----------------
// Also zeroes g_deg / g_flag at entry (replaces the memset launch; hist runs strictly after).
__global__ void __launch_bounds__(128) sgemm1k(const float* __restrict__ A,
                                               const float* __restrict__ B,
                                               float* __restrict__ C,
                                               const float* __restrict__ att_src,
                                               const float* __restrict__ att_dst,
                                               int M) {
    // fold in scratch zeroing (one element per thread; grid covers >= M threads)
    {
        int t = blockIdx.x * 128 + threadIdx.x;
        if (t < M) g_deg[t] = 0;
        if (t < 64) g_flag[t] = 0;
    }

    const int K = 512, N = 64;
    __shared__ float As[2][16][128];
    __shared__ float Bs[2][16][64];
    int tid = threadIdx.x;
    int tx = tid & 7, ty = tid >> 3;
    int row0 = blockIdx.x * 128;

    int aRowG = row0 + tid;
    if (aRowG >= M) aRowG = M - 1;
    const float* Arow = A + (size_t)aRowG * K;

    int brow = tid >> 3, bc = (tid & 7) * 8;

    float acc[8][8] = {};
    float4 rA[4], rB0, rB1;

    {
        rA[0] = *(const float4*)&Arow[0];
        rA[1] = *(const float4*)&Arow[4];
        rA[2] = *(const float4*)&Arow[8];
        rA[3] = *(const float4*)&Arow[12];
        rB0 = *(const float4*)&B[(size_t)brow * N + bc];
        rB1 = *(const float4*)&B[(size_t)brow * N + bc + 4];
#pragma unroll
        for (int q = 0; q < 4; q++) {
            As[0][q * 4 + 0][tid] = ((float*)&rA[q])[0];
            As[0][q * 4 + 1][tid] = ((float*)&rA[q])[1];
            As[0][q * 4 + 2][tid] = ((float*)&rA[q])[2];
            As[0][q * 4 + 3][tid] = ((float*)&rA[q])[3];
        }
        *(float4*)&Bs[0][brow][bc] = rB0;
        *(float4*)&Bs[0][brow][bc + 4] = rB1;
    }
    __syncthreads();

    int buf = 0;
    for (int k0 = 0; k0 < K; k0 += 16, buf ^= 1) {
        bool more = (k0 + 16 < K);
        if (more) {
            rA[0] = *(const float4*)&Arow[k0 + 16];
            rA[1] = *(const float4*)&Arow[k0 + 20];
            rA[2] = *(const float4*)&Arow[k0 + 24];
            rA[3] = *(const float4*)&Arow[k0 + 28];
            rB0 = *(const float4*)&B[(size_t)(k0 + 16 + brow) * N + bc];
            rB1 = *(const float4*)&B[(size_t)(k0 + 16 + brow) * N + bc + 4];
        }
#pragma unroll
        for (int kk = 0; kk < 16; kk++) {
            float a[8], b[8];
            *(float4*)&a[0] = *(float4*)&As[buf][kk][ty * 8];
            *(float4*)&a[4] = *(float4*)&As[buf][kk][ty * 8 + 4];
            *(float4*)&b[0] = *(float4*)&Bs[buf][kk][tx * 8];
            *(float4*)&b[4] = *(float4*)&Bs[buf][kk][tx * 8 + 4];
#pragma unroll
            for (int i = 0; i < 8; i++)
#pragma unroll
                for (int j = 0; j < 8; j++)
                    acc[i][j] += a[i] * b[j];
        }
        if (more) {
            int nb = buf ^ 1;
#pragma unroll
            for (int q = 0; q < 4; q++) {
                As[nb][q * 4 + 0][tid] = ((float*)&rA[q])[0];
                As[nb][q * 4 + 1][tid] = ((float*)&rA[q])[1];
                As[nb][q * 4 + 2][tid] = ((float*)&rA[q])[2];
                As[nb][q * 4 + 3][tid] = ((float*)&rA[q])[3];
            }
            *(float4*)&Bs[nb][brow][bc] = rB0;
            *(float4*)&Bs[nb][brow][bc + 4] = rB1;
        }
        __syncthreads();
    }

    float asv[8], adv[8];
#pragma unroll
    for (int j = 0; j < 8; j++) {
        asv[j] = att_src[tx * 8 + j];
        adv[j] = att_dst[tx * 8 + j];
    }
#pragma unroll
    for (int i = 0; i < 8; i++) {
        int r = row0 + ty * 8 + i;
        if (r < M) {
            *(float4*)&C[(size_t)r * N + tx * 8] = *(float4*)&acc[i][0];
            *(float4*)&C[(size_t)r * N + tx * 8 + 4] = *(float4*)&acc[i][4];
            float as = 0.f, ad = 0.f;
#pragma unroll
            for (int j = 0; j < 8; j++) {
                as += acc[i][j] * asv[j];
                ad += acc[i][j] * adv[j];
            }
            g_asrc1[r * 8 + tx] = as;
            g_adst1[r * 8 + tx] = ad;
        }
    }
}

// ---------------- CSR build ----------------
__global__ void hist_dst(const int* __restrict__ ei, int E) {
    int e = blockIdx.x * blockDim.x + threadIdx.x;
    if (e < E) atomicAdd(&g_deg[ei[E + e]], 1);
}

// single-pass decoupled-lookback exclusive scan (49 blocks, all co-resident)
__global__ void scan_onepass(int Nn, int nChunks) {
    __shared__ int wsum[32];
    __shared__ int s_total, s_prev;
    int b = blockIdx.x;
    int i = b * 1024 + threadIdx.x;
    int lane = threadIdx.x & 31, wid = threadIdx.x >> 5;
    int v = (i < Nn) ? g_deg[i] : 0;
    int sc = v;
#pragma unroll
    for (int o = 1; o < 32; o <<= 1) {
        int t = __shfl_up_sync(~0u, sc, o);
        if (lane >= o) sc += t;
    }
    if (lane == 31) wsum[wid] = sc;
    __syncthreads();
    if (wid == 0) {
        int ws = wsum[lane];
#pragma unroll
        for (int o = 1; o < 32; o <<= 1) {
            int t = __shfl_up_sync(~0u, ws, o);
            if (lane >= o) ws += t;
        }
        wsum[lane] = ws;
    }
    __syncthreads();
    int excl = sc - v + (wid > 0 ? wsum[wid - 1] : 0);
    if (threadIdx.x == 1023) s_total = excl + v;
    __syncthreads();
    if (threadIdx.x == 0) {
        int prev = 0;
        if (b > 0) {
            while (atomicAdd(&g_flag[b - 1], 0) == 0) { }
            prev = g_incl[b - 1];
        }
        s_prev = prev;
        g_incl[b] = prev + s_total;
        __threadfence();
        atomicExch(&g_flag[b], 1);
    }
    __syncthreads();
    int base = s_prev;
    if (i < Nn) {
        int s = excl + base;
        g_start[i] = s;
        g_cursor[i] = s;
    }
    if (b == nChunks - 1 && threadIdx.x == 1023) g_start[Nn] = base + s_total;
}

__global__ void scatter_csr(const int* __restrict__ ei, int E) {
    int e = blockIdx.x * blockDim.x + threadIdx.x;
    if (e >= E) return;
    int d = ei[E + e];
    int pos = atomicAdd(&g_cursor[d], 1);
    g_csrc[pos] = ei[e];
}

// ---------------- layer-2 attention logits ----------------
__global__ void node_attn2(const float* __restrict__ att_src, const float* __restrict__ att_dst, int Nn) {
    int i = blockIdx.x * blockDim.x + threadIdx.x;
    if (i >= Nn) return;
    const float* h = &g_h2[i * 40];
    float as = 0.f, ad = 0.f;
#pragma unroll
    for (int c = 0; c < 40; c++) {
        float v = h[c];
        as += v * att_src[c];
        ad += v * att_dst[c];
    }
    g_as2[i] = as;
    g_ad2[i] = ad;
}

// ---------------- SGEMM2 (64x64x16 tiles) ----------------
__global__ void sgemm64(const float* __restrict__ A, const float* __restrict__ B,
                        float* __restrict__ C, int M, int N, int K) {
    __shared__ float As[16][64];
    __shared__ float Bs[16][64];
    int tid = threadIdx.x;
    int tx = tid & 15, ty = tid >> 4;
    int row0 = blockIdx.x * 64;

    int arow = tid >> 2, ak = (tid & 3) << 2;
    int brow = tid >> 4, bc = (tid & 15) << 2;

    float acc[4][4] = {};

    for (int k0 = 0; k0 < K; k0 += 16) {
        float4 av = make_float4(0.f, 0.f, 0.f, 0.f);
        if (row0 + arow < M)
            av = *(const float4*)&A[(size_t)(row0 + arow) * K + k0 + ak];
        As[ak + 0][arow] = av.x;
        As[ak + 1][arow] = av.y;
        As[ak + 2][arow] = av.z;
        As[ak + 3][arow] = av.w;

        float4 bv = make_float4(0.f, 0.f, 0.f, 0.f);
        if (bc < N)
            bv = *(const float4*)&B[(size_t)(k0 + brow) * N + bc];
        *(float4*)&Bs[brow][bc] = bv;

        __syncthreads();
#pragma unroll
        for (int kk = 0; kk < 16; kk++) {
            float a0 = As[kk][ty * 4 + 0];
            float a1 = As[kk][ty * 4 + 1];
            float a2 = As[kk][ty * 4 + 2];
            float a3 = As[kk][ty * 4 + 3];
            float4 b = *(float4*)&Bs[kk][tx * 4];
            acc[0][0] += a0 * b.x; acc[0][1] += a0 * b.y; acc[0][2] += a0 * b.z; acc[0][3] += a0 * b.w;
            acc[1][0] += a1 * b.x; acc[1][1] += a1 * b.y; acc[1][2] += a1 * b.z; acc[1][3] += a1 * b.w;
            acc[2][0] += a2 * b.x; acc[2][1] += a2 * b.y; acc[2][2] += a2 * b.z; acc[2][3] += a2 * b.w;
            acc[3][0] += a3 * b.x; acc[3][1] += a3 * b.y; acc[3][2] += a3 * b.z; acc[3][3] += a3 * b.w;
        }
        __syncthreads();
    }
#pragma unroll
    for (int i = 0; i < 4; i++) {
        int r = row0 + ty * 4 + i;
        if (r >= M) continue;
#pragma unroll
        for (int j = 0; j < 4; j++) {
            int c = tx * 4 + j;
            if (c < N) C[(size_t)r * N + c] = acc[i][j];
        }
    }
}

// ---------------- Layer 1 aggregation: warp per node ----------------
__global__ void __launch_bounds__(256) agg1(const float* __restrict__ b1, int Nn) {
    int gw = (blockIdx.x * blockDim.x + threadIdx.x) >> 5;
    if (gw >= Nn) return;
    int i = gw;
    int lane = threadIdx.x & 31;
    int h = lane >> 2;
    const float2* h1f2 = (const float2*)g_h1;

    float adst_w = g_adst1[i * 8 + (lane & 7)];
    float wself = __expf(leaky(g_asrc1[i * 8 + h] + g_adst1[i * 8 + h]));
    float denom = wself;
    float2 hv0 = h1f2[i * 32 + lane];
    float2 acc = make_float2(wself * hv0.x, wself * hv0.y);

    int st = g_start[i], en = g_start[i + 1];
    for (int e0 = st; e0 < en; e0 += 4) {
        int idx = e0 + (lane >> 3);
        bool valid = idx < en;
        int s = valid ? g_csrc[idx] : 0;
        float w = valid ? __expf(leaky(g_asrc1[s * 8 + (lane & 7)] + adst_w)) : 0.f;
#pragma unroll
        for (int j = 0; j < 4; j++) {
            int sj = __shfl_sync(~0u, s, j * 8);
            float wj = __shfl_sync(~0u, w, j * 8 + h);
            float2 hv = h1f2[sj * 32 + lane];
            acc.x += wj * hv.x;
            acc.y += wj * hv.y;
            denom += wj;
        }
    }
    float inv = 1.f / (denom + 1e-16f);
    float2 bb = ((const float2*)b1)[lane];
    float vx = acc.x * inv + bb.x;
    float vy = acc.y * inv + bb.y;
    ((float2*)g_h2in)[i * 32 + lane] = make_float2(vx > 0.f ? vx : 0.f, vy > 0.f ? vy : 0.f);
}

// ---------------- Layer 2 aggregation: warp per node ----------------
__global__ void __launch_bounds__(256) agg2(const float* __restrict__ b2,
                                            float* __restrict__ out, int Nn) {
    int gw = (blockIdx.x * blockDim.x + threadIdx.x) >> 5;
    if (gw >= Nn) return;
    int i = gw;
    int lane = threadIdx.x & 31;
    int cl = lane < 20 ? lane : 0;
    const float2* h2f2 = (const float2*)g_h2;

    float ad = g_ad2[i];
    float wself = __expf(leaky(g_as2[i] + ad));
    float denom = wself;
    float2 hv0 = h2f2[i * 20 + cl];
    float2 acc = make_float2(wself * hv0.x, wself * hv0.y);

    int st = g_start[i], en = g_start[i + 1];
    for (int e0 = st; e0 < en; e0 += 32) {
        int idx = e0 + lane;
        bool valid = idx < en;
        int s = valid ? g_csrc[idx] : 0;
        float w = valid ? __expf(leaky(g_as2[s] + ad)) : 0.f;
        int nleft = en - e0;
        int cnt = nleft < 32 ? nleft : 32;
#pragma unroll 8
        for (int j = 0; j < cnt; j++) {
            int sj = __shfl_sync(~0u, s, j);
            float wj = __shfl_sync(~0u, w, j);
            float2 hv = h2f2[sj * 20 + cl];
            acc.x += wj * hv.x;
            acc.y += wj * hv.y;
            denom += wj;
        }
    }
    float inv = 1.f / (denom + 1e-16f);
    float2 bb = ((const float2*)b2)[cl];
    float vx = acc.x * inv + bb.x;
    float vy = acc.y * inv + bb.y;

    float mloc = (lane < 20) ? fmaxf(vx, vy) : -1e30f;
#pragma unroll
    for (int o = 16; o > 0; o >>= 1) mloc = fmaxf(mloc, __shfl_xor_sync(~0u, mloc, o));
    float sloc = (lane < 20) ? (__expf(vx - mloc) + __expf(vy - mloc)) : 0.f;
#pragma unroll
    for (int o = 16; o > 0; o >>= 1) sloc += __shfl_xor_sync(~0u, sloc, o);
    float lse = mloc + logf(sloc);
    if (lane < 20)
        ((float2*)out)[i * 20 + lane] = make_float2(vx - lse, vy - lse);
}

// ---------------- launch ----------------
extern "C" void kernel_launch(void* const* d_in, const int* in_sizes, int n_in,
                              void* d_out, int out_size) {
    const float* x   = (const float*)d_in[0];
    const int*   ei  = (const int*)d_in[1];
    const float* W1  = (const float*)d_in[2];
    const float* as1 = (const float*)d_in[3];
    const float* ad1 = (const float*)d_in[4];
    const float* b1  = (const float*)d_in[5];
    const float* W2  = (const float*)d_in[6];
    const float* as2 = (const float*)d_in[7];
    const float* ad2 = (const float*)d_in[8];
    const float* b2  = (const float*)d_in[9];
    float* out = (float*)d_out;

    int Nn = in_sizes[0] / 512;   // 50000
    int E  = in_sizes[1] / 2;     // 1600000

    void *ph1, *ph2in, *ph2;
    cudaGetSymbolAddress(&ph1, g_h1);
    cudaGetSymbolAddress(&ph2in, g_h2in);
    cudaGetSymbolAddress(&ph2, g_h2);

    const int T = 256;
    int nChunks = (Nn + 1023) / 1024;   // 49
    int aggBlocks = (Nn + 7) / 8;

    // 1: gemm1 (+ zero deg/flags in-kernel; hist is stream-ordered after)
    sgemm1k<<<(Nn + 127) / 128, 128>>>(x, W1, (float*)ph1, as1, ad1, Nn);
    // 2-4: CSR build
    hist_dst<<<(E + T - 1) / T, T>>>(ei, E);
    scan_onepass<<<nChunks, 1024>>>(Nn, nChunks);
    scatter_csr<<<(E + T - 1) / T, T>>>(ei, E);
    // 5: layer-1 aggregation (profiled launch)
    agg1<<<aggBlocks, T>>>(b1, Nn);
    // 6-8: layer 2
    sgemm64<<<(Nn + 63) / 64, T>>>((const float*)ph2in, W2, (float*)ph2, Nn, 40, 64);
    node_attn2<<<(Nn + T - 1) / T, T>>>(as2, ad2, Nn);
    agg2<<<aggBlocks, T>>>(b2, out, Nn);
}

// round 11
// speedup vs baseline: 1.1960x; 1.1960x over previous
#include <cuda_runtime.h>
#include <cuda_bf16.h>

#define NMAX 50000
#define EMAX 1700000

// ---------------- scratch ----------------
__device__ float g_h1[NMAX * 64];
__device__ float g_asrc1[NMAX * 8];
__device__ float g_adst1[NMAX * 8];
__device__ float g_h2in[NMAX * 64];
__device__ float g_h2[NMAX * 40];
__device__ float g_as2[NMAX];
__device__ float g_ad2[NMAX];
// CSR
__device__ int g_deg[NMAX];
__device__ int g_start[NMAX + 1];
__device__ int g_cursor[NMAX];
__device__ int g_csrc[EMAX];
__device__ int g_bsum[64];

__device__ __forceinline__ float leaky(float e) { return e >= 0.f ? e : 0.2f * e; }

// packed f32x2 helpers
__device__ __forceinline__ unsigned long long packf2(float a) {
    unsigned long long r;
    asm("mov.b64 %0, {%1, %1};" : "=l"(r) : "f"(a));
    return r;
}
__device__ __forceinline__ void fma2(unsigned long long& d, unsigned long long a, unsigned long long b) {
    asm("fma.rn.f32x2 %0, %1, %2, %3;" : "=l"(d) : "l"(a), "l"(b), "l"(d));
}

// ---------------- SGEMM1: C[M,64] = A[M,512] @ B[512,64] + fused attn logits ----------------
// BM=128 BN=64 BK=16, 128 threads, 8x8 microtile via packed f32x2 FMA, double-buffered.
__global__ void __launch_bounds__(128) sgemm1k(const float* __restrict__ A,
                                               const float* __restrict__ B,
                                               float* __restrict__ C,
                                               const float* __restrict__ att_src,
                                               const float* __restrict__ att_dst,
                                               int M) {
    const int K = 512, N = 64;
    __shared__ float As[2][16][128];
    __shared__ float Bs[2][16][64];
    int tid = threadIdx.x;
    int tx = tid & 7, ty = tid >> 3;
    int row0 = blockIdx.x * 128;

    int aRowG = row0 + tid;
    if (aRowG >= M) aRowG = M - 1;
    const float* Arow = A + (size_t)aRowG * K;

    int brow = tid >> 3, bc = (tid & 7) * 8;

    unsigned long long acc2[8][4] = {};   // 8 rows x 4 packed column-pairs
    float4 rA[4], rB0, rB1;

    {
        rA[0] = *(const float4*)&Arow[0];
        rA[1] = *(const float4*)&Arow[4];
        rA[2] = *(const float4*)&Arow[8];
        rA[3] = *(const float4*)&Arow[12];
        rB0 = *(const float4*)&B[(size_t)brow * N + bc];
        rB1 = *(const float4*)&B[(size_t)brow * N + bc + 4];
#pragma unroll
        for (int q = 0; q < 4; q++) {
            As[0][q * 4 + 0][tid] = ((float*)&rA[q])[0];
            As[0][q * 4 + 1][tid] = ((float*)&rA[q])[1];
            As[0][q * 4 + 2][tid] = ((float*)&rA[q])[2];
            As[0][q * 4 + 3][tid] = ((float*)&rA[q])[3];
        }
        *(float4*)&Bs[0][brow][bc] = rB0;
        *(float4*)&Bs[0][brow][bc + 4] = rB1;
    }
    __syncthreads();

    int buf = 0;
    for (int k0 = 0; k0 < K; k0 += 16, buf ^= 1) {
        bool more = (k0 + 16 < K);
        if (more) {
            rA[0] = *(const float4*)&Arow[k0 + 16];
            rA[1] = *(const float4*)&Arow[k0 + 20];
            rA[2] = *(const float4*)&Arow[k0 + 24];
            rA[3] = *(const float4*)&Arow[k0 + 28];
            rB0 = *(const float4*)&B[(size_t)(k0 + 16 + brow) * N + bc];
            rB1 = *(const float4*)&B[(size_t)(k0 + 16 + brow) * N + bc + 4];
        }
#pragma unroll
        for (int kk = 0; kk < 16; kk++) {
            float a[8];
            *(float4*)&a[0] = *(float4*)&As[buf][kk][ty * 8];
            *(float4*)&a[4] = *(float4*)&As[buf][kk][ty * 8 + 4];
            unsigned long long b2[4];
            *(ulonglong2*)&b2[0] = *(ulonglong2*)&Bs[buf][kk][tx * 8];
            *(ulonglong2*)&b2[2] = *(ulonglong2*)&Bs[buf][kk][tx * 8 + 4];
#pragma unroll
            for (int i = 0; i < 8; i++) {
                unsigned long long a2 = packf2(a[i]);
                fma2(acc2[i][0], a2, b2[0]);
                fma2(acc2[i][1], a2, b2[1]);
                fma2(acc2[i][2], a2, b2[2]);
                fma2(acc2[i][3], a2, b2[3]);
            }
        }
        if (more) {
            int nb = buf ^ 1;
#pragma unroll
            for (int q = 0; q < 4; q++) {
                As[nb][q * 4 + 0][tid] = ((float*)&rA[q])[0];
                As[nb][q * 4 + 1][tid] = ((float*)&rA[q])[1];
                As[nb][q * 4 + 2][tid] = ((float*)&rA[q])[2];
                As[nb][q * 4 + 3][tid] = ((float*)&rA[q])[3];
            }
            *(float4*)&Bs[nb][brow][bc] = rB0;
            *(float4*)&Bs[nb][brow][bc + 4] = rB1;
        }
        __syncthreads();
    }

    float asv[8], adv[8];
#pragma unroll
    for (int j = 0; j < 8; j++) {
        asv[j] = att_src[tx * 8 + j];
        adv[j] = att_dst[tx * 8 + j];
    }
#pragma unroll
    for (int i = 0; i < 8; i++) {
        int r = row0 + ty * 8 + i;
        if (r < M) {
            const float* accf = (const float*)&acc2[i][0];   // 8 floats, col order
            *(float4*)&C[(size_t)r * N + tx * 8] = *(const float4*)&accf[0];
            *(float4*)&C[(size_t)r * N + tx * 8 + 4] = *(const float4*)&accf[4];
            float as = 0.f, ad = 0.f;
#pragma unroll
            for (int j = 0; j < 8; j++) {
                as += accf[j] * asv[j];
                ad += accf[j] * adv[j];
            }
            g_asrc1[r * 8 + tx] = as;
            g_adst1[r * 8 + tx] = ad;
        }
    }
}

// ---------------- CSR build ----------------
__global__ void hist_dst(const int* __restrict__ ei, int E) {
    int e = blockIdx.x * blockDim.x + threadIdx.x;
    if (e < E) atomicAdd(&g_deg[ei[E + e]], 1);
}

__global__ void scan_local(int Nn) {
    __shared__ int wsum[32];
    int i = blockIdx.x * 1024 + threadIdx.x;
    int lane = threadIdx.x & 31, wid = threadIdx.x >> 5;
    int v = (i < Nn) ? g_deg[i] : 0;
    int sc = v;
#pragma unroll
    for (int o = 1; o < 32; o <<= 1) {
        int t = __shfl_up_sync(~0u, sc, o);
        if (lane >= o) sc += t;
    }
    if (lane == 31) wsum[wid] = sc;
    __syncthreads();
    if (wid == 0) {
        int ws = wsum[lane];
#pragma unroll
        for (int o = 1; o < 32; o <<= 1) {
            int t = __shfl_up_sync(~0u, ws, o);
            if (lane >= o) ws += t;
        }
        wsum[lane] = ws;
    }
    __syncthreads();
    int excl = sc - v + (wid > 0 ? wsum[wid - 1] : 0);
    if (i < Nn) g_start[i] = excl;
    if (threadIdx.x == 1023) g_bsum[blockIdx.x] = excl + v;
}

__global__ void scan_spine(int nb, int Nn) {
    int lane = threadIdx.x;
    int v0 = (lane * 2 < nb) ? g_bsum[lane * 2] : 0;
    int v1 = (lane * 2 + 1 < nb) ? g_bsum[lane * 2 + 1] : 0;
    int s = v0 + v1;
    int sc = s;
#pragma unroll
    for (int o = 1; o < 32; o <<= 1) {
        int t = __shfl_up_sync(~0u, sc, o);
        if (lane >= o) sc += t;
    }
    int excl = sc - s;
    if (lane * 2 < nb) g_bsum[lane * 2] = excl;
    if (lane * 2 + 1 < nb) g_bsum[lane * 2 + 1] = excl + v0;
    if (lane == 31) g_start[Nn] = sc;
}

__global__ void scan_add(int Nn) {
    int i = blockIdx.x * blockDim.x + threadIdx.x;
    if (i >= Nn) return;
    int s = g_start[i] + g_bsum[i >> 10];
    g_start[i] = s;
    g_cursor[i] = s;
}

__global__ void scatter_csr(const int* __restrict__ ei, int E) {
    int e = blockIdx.x * blockDim.x + threadIdx.x;
    if (e >= E) return;
    int d = ei[E + e];
    int pos = atomicAdd(&g_cursor[d], 1);
    g_csrc[pos] = ei[e];
}

// ---------------- layer-2 attention logits ----------------
__global__ void node_attn2(const float* __restrict__ att_src, const float* __restrict__ att_dst, int Nn) {
    int i = blockIdx.x * blockDim.x + threadIdx.x;
    if (i >= Nn) return;
    const float* h = &g_h2[i * 40];
    float as = 0.f, ad = 0.f;
#pragma unroll
    for (int c = 0; c < 40; c++) {
        float v = h[c];
        as += v * att_src[c];
        ad += v * att_dst[c];
    }
    g_as2[i] = as;
    g_ad2[i] = ad;
}

// ---------------- SGEMM2 (64x64x16 tiles) ----------------
__global__ void sgemm64(const float* __restrict__ A, const float* __restrict__ B,
                        float* __restrict__ C, int M, int N, int K) {
    __shared__ float As[16][64];
    __shared__ float Bs[16][64];
    int tid = threadIdx.x;
    int tx = tid & 15, ty = tid >> 4;
    int row0 = blockIdx.x * 64;

    int arow = tid >> 2, ak = (tid & 3) << 2;
    int brow = tid >> 4, bc = (tid & 15) << 2;

    float acc[4][4] = {};

    for (int k0 = 0; k0 < K; k0 += 16) {
        float4 av = make_float4(0.f, 0.f, 0.f, 0.f);
        if (row0 + arow < M)
            av = *(const float4*)&A[(size_t)(row0 + arow) * K + k0 + ak];
        As[ak + 0][arow] = av.x;
        As[ak + 1][arow] = av.y;
        As[ak + 2][arow] = av.z;
        As[ak + 3][arow] = av.w;

        float4 bv = make_float4(0.f, 0.f, 0.f, 0.f);
        if (bc < N)
            bv = *(const float4*)&B[(size_t)(k0 + brow) * N + bc];
        *(float4*)&Bs[brow][bc] = bv;

        __syncthreads();
#pragma unroll
        for (int kk = 0; kk < 16; kk++) {
            float a0 = As[kk][ty * 4 + 0];
            float a1 = As[kk][ty * 4 + 1];
            float a2 = As[kk][ty * 4 + 2];
            float a3 = As[kk][ty * 4 + 3];
            float4 b = *(float4*)&Bs[kk][tx * 4];
            acc[0][0] += a0 * b.x; acc[0][1] += a0 * b.y; acc[0][2] += a0 * b.z; acc[0][3] += a0 * b.w;
            acc[1][0] += a1 * b.x; acc[1][1] += a1 * b.y; acc[1][2] += a1 * b.z; acc[1][3] += a1 * b.w;
            acc[2][0] += a2 * b.x; acc[2][1] += a2 * b.y; acc[2][2] += a2 * b.z; acc[2][3] += a2 * b.w;
            acc[3][0] += a3 * b.x; acc[3][1] += a3 * b.y; acc[3][2] += a3 * b.z; acc[3][3] += a3 * b.w;
        }
        __syncthreads();
    }
#pragma unroll
    for (int i = 0; i < 4; i++) {
        int r = row0 + ty * 4 + i;
        if (r >= M) continue;
#pragma unroll
        for (int j = 0; j < 4; j++) {
            int c = tx * 4 + j;
            if (c < N) C[(size_t)r * N + c] = acc[i][j];
        }
    }
}

// ---------------- Layer 1 aggregation: warp per node ----------------
__global__ void __launch_bounds__(256) agg1(const float* __restrict__ b1, int Nn) {
    int gw = (blockIdx.x * blockDim.x + threadIdx.x) >> 5;
    if (gw >= Nn) return;
    int i = gw;
    int lane = threadIdx.x & 31;
    int h = lane >> 2;
    const float2* h1f2 = (const float2*)g_h1;

    float adst_w = g_adst1[i * 8 + (lane & 7)];
    float wself = __expf(leaky(g_asrc1[i * 8 + h] + g_adst1[i * 8 + h]));
    float denom = wself;
    float2 hv0 = h1f2[i * 32 + lane];
    float2 acc = make_float2(wself * hv0.x, wself * hv0.y);

    int st = g_start[i], en = g_start[i + 1];
    for (int e0 = st; e0 < en; e0 += 4) {
        int idx = e0 + (lane >> 3);
        bool valid = idx < en;
        int s = valid ? g_csrc[idx] : 0;
        float w = valid ? __expf(leaky(g_asrc1[s * 8 + (lane & 7)] + adst_w)) : 0.f;
#pragma unroll
        for (int j = 0; j < 4; j++) {
            int sj = __shfl_sync(~0u, s, j * 8);
            float wj = __shfl_sync(~0u, w, j * 8 + h);
            float2 hv = h1f2[sj * 32 + lane];
            acc.x += wj * hv.x;
            acc.y += wj * hv.y;
            denom += wj;
        }
    }
    float inv = 1.f / (denom + 1e-16f);
    float2 bb = ((const float2*)b1)[lane];
    float vx = acc.x * inv + bb.x;
    float vy = acc.y * inv + bb.y;
    ((float2*)g_h2in)[i * 32 + lane] = make_float2(vx > 0.f ? vx : 0.f, vy > 0.f ? vy : 0.f);
}

// ---------------- Layer 2 aggregation: warp per node ----------------
__global__ void __launch_bounds__(256) agg2(const float* __restrict__ b2,
                                            float* __restrict__ out, int Nn) {
    int gw = (blockIdx.x * blockDim.x + threadIdx.x) >> 5;
    if (gw >= Nn) return;
    int i = gw;
    int lane = threadIdx.x & 31;
    int cl = lane < 20 ? lane : 0;
    const float2* h2f2 = (const float2*)g_h2;

    float ad = g_ad2[i];
    float wself = __expf(leaky(g_as2[i] + ad));
    float denom = wself;
    float2 hv0 = h2f2[i * 20 + cl];
    float2 acc = make_float2(wself * hv0.x, wself * hv0.y);

    int st = g_start[i], en = g_start[i + 1];
    for (int e0 = st; e0 < en; e0 += 32) {
        int idx = e0 + lane;
        bool valid = idx < en;
        int s = valid ? g_csrc[idx] : 0;
        float w = valid ? __expf(leaky(g_as2[s] + ad)) : 0.f;
        int nleft = en - e0;
        int cnt = nleft < 32 ? nleft : 32;
#pragma unroll 8
        for (int j = 0; j < cnt; j++) {
            int sj = __shfl_sync(~0u, s, j);
            float wj = __shfl_sync(~0u, w, j);
            float2 hv = h2f2[sj * 20 + cl];
            acc.x += wj * hv.x;
            acc.y += wj * hv.y;
            denom += wj;
        }
    }
    float inv = 1.f / (denom + 1e-16f);
    float2 bb = ((const float2*)b2)[cl];
    float vx = acc.x * inv + bb.x;
    float vy = acc.y * inv + bb.y;

    float mloc = (lane < 20) ? fmaxf(vx, vy) : -1e30f;
#pragma unroll
    for (int o = 16; o > 0; o >>= 1) mloc = fmaxf(mloc, __shfl_xor_sync(~0u, mloc, o));
    float sloc = (lane < 20) ? (__expf(vx - mloc) + __expf(vy - mloc)) : 0.f;
#pragma unroll
    for (int o = 16; o > 0; o >>= 1) sloc += __shfl_xor_sync(~0u, sloc, o);
    float lse = mloc + logf(sloc);
    if (lane < 20)
        ((float2*)out)[i * 20 + lane] = make_float2(vx - lse, vy - lse);
}

// ---------------- launch ----------------
extern "C" void kernel_launch(void* const* d_in, const int* in_sizes, int n_in,
                              void* d_out, int out_size) {
    const float* x   = (const float*)d_in[0];
    const int*   ei  = (const int*)d_in[1];
    const float* W1  = (const float*)d_in[2];
    const float* as1 = (const float*)d_in[3];
    const float* ad1 = (const float*)d_in[4];
    const float* b1  = (const float*)d_in[5];
    const float* W2  = (const float*)d_in[6];
    const float* as2 = (const float*)d_in[7];
    const float* ad2 = (const float*)d_in[8];
    const float* b2  = (const float*)d_in[9];
    float* out = (float*)d_out;

    int Nn = in_sizes[0] / 512;   // 50000
    int E  = in_sizes[1] / 2;     // 1600000

    void *ph1, *ph2in, *ph2, *pdeg;
    cudaGetSymbolAddress(&ph1, g_h1);
    cudaGetSymbolAddress(&ph2in, g_h2in);
    cudaGetSymbolAddress(&ph2, g_h2);
    cudaGetSymbolAddress(&pdeg, g_deg);

    const int T = 256;
    int nChunks = (Nn + 1023) / 1024;
    int aggBlocks = (Nn + 7) / 8;

    // CSR build (shared by both layers)
    cudaMemsetAsync(pdeg, 0, (size_t)Nn * sizeof(int));
    hist_dst<<<(E + T - 1) / T, T>>>(ei, E);
    scan_local<<<nChunks, 1024>>>(Nn);
    scan_spine<<<1, 32>>>(nChunks, Nn);
    scan_add<<<(Nn + T - 1) / T, T>>>(Nn);
    scatter_csr<<<(E + T - 1) / T, T>>>(ei, E);

    // layer 1 (attn logits fused into GEMM epilogue, f32x2 packed FMA)
    sgemm1k<<<(Nn + 127) / 128, 128>>>(x, W1, (float*)ph1, as1, ad1, Nn);
    agg1<<<aggBlocks, T>>>(b1, Nn);

    // layer 2
    sgemm64<<<(Nn + 63) / 64, T>>>((const float*)ph2in, W2, (float*)ph2, Nn, 40, 64);
    node_attn2<<<(Nn + T - 1) / T, T>>>(as2, ad2, Nn);
    agg2<<<aggBlocks, T>>>(b2, out, Nn);
}

// round 12
// speedup vs baseline: 1.3030x; 1.0895x over previous
#include <cuda_runtime.h>
#include <cuda_bf16.h>

#define NMAX 50000
#define EMAX 1700000

// ---------------- scratch ----------------
__device__ float g_h1[NMAX * 64];
__device__ float g_asrc1[NMAX * 8];
__device__ float g_adst1[NMAX * 8];
__device__ float g_h2in[NMAX * 64];
__device__ float g_h2[NMAX * 40];
__device__ float g_as2[NMAX];
__device__ float g_ad2[NMAX];
// CSR
__device__ int g_deg[NMAX];
__device__ int g_start[NMAX + 1];
__device__ int g_cursor[NMAX];
__device__ int g_csrc[EMAX];
__device__ int g_bsum[64];

__device__ __forceinline__ float leaky(float e) { return e >= 0.f ? e : 0.2f * e; }

// packed f32x2 helpers
__device__ __forceinline__ unsigned long long packf2(float a) {
    unsigned long long r;
    asm("mov.b64 %0, {%1, %1};" : "=l"(r) : "f"(a));
    return r;
}
__device__ __forceinline__ void fma2(unsigned long long& d, unsigned long long a, unsigned long long b) {
    asm("fma.rn.f32x2 %0, %1, %2, %3;" : "=l"(d) : "l"(a), "l"(b), "l"(d));
}

// ---------------- SGEMM1: C[M,64] = A[M,512] @ B[512,64] + fused attn logits ----------------
__global__ void __launch_bounds__(128) sgemm1k(const float* __restrict__ A,
                                               const float* __restrict__ B,
                                               float* __restrict__ C,
                                               const float* __restrict__ att_src,
                                               const float* __restrict__ att_dst,
                                               int M) {
    const int K = 512, N = 64;
    __shared__ float As[2][16][128];
    __shared__ float Bs[2][16][64];
    int tid = threadIdx.x;
    int tx = tid & 7, ty = tid >> 3;
    int row0 = blockIdx.x * 128;

    int aRowG = row0 + tid;
    if (aRowG >= M) aRowG = M - 1;
    const float* Arow = A + (size_t)aRowG * K;

    int brow = tid >> 3, bc = (tid & 7) * 8;

    unsigned long long acc2[8][4] = {};
    float4 rA[4], rB0, rB1;

    {
        rA[0] = *(const float4*)&Arow[0];
        rA[1] = *(const float4*)&Arow[4];
        rA[2] = *(const float4*)&Arow[8];
        rA[3] = *(const float4*)&Arow[12];
        rB0 = *(const float4*)&B[(size_t)brow * N + bc];
        rB1 = *(const float4*)&B[(size_t)brow * N + bc + 4];
#pragma unroll
        for (int q = 0; q < 4; q++) {
            As[0][q * 4 + 0][tid] = ((float*)&rA[q])[0];
            As[0][q * 4 + 1][tid] = ((float*)&rA[q])[1];
            As[0][q * 4 + 2][tid] = ((float*)&rA[q])[2];
            As[0][q * 4 + 3][tid] = ((float*)&rA[q])[3];
        }
        *(float4*)&Bs[0][brow][bc] = rB0;
        *(float4*)&Bs[0][brow][bc + 4] = rB1;
    }
    __syncthreads();

    int buf = 0;
    for (int k0 = 0; k0 < K; k0 += 16, buf ^= 1) {
        bool more = (k0 + 16 < K);
        if (more) {
            rA[0] = *(const float4*)&Arow[k0 + 16];
            rA[1] = *(const float4*)&Arow[k0 + 20];
            rA[2] = *(const float4*)&Arow[k0 + 24];
            rA[3] = *(const float4*)&Arow[k0 + 28];
            rB0 = *(const float4*)&B[(size_t)(k0 + 16 + brow) * N + bc];
            rB1 = *(const float4*)&B[(size_t)(k0 + 16 + brow) * N + bc + 4];
        }
#pragma unroll
        for (int kk = 0; kk < 16; kk++) {
            float a[8];
            *(float4*)&a[0] = *(float4*)&As[buf][kk][ty * 8];
            *(float4*)&a[4] = *(float4*)&As[buf][kk][ty * 8 + 4];
            unsigned long long b2[4];
            *(ulonglong2*)&b2[0] = *(ulonglong2*)&Bs[buf][kk][tx * 8];
            *(ulonglong2*)&b2[2] = *(ulonglong2*)&Bs[buf][kk][tx * 8 + 4];
#pragma unroll
            for (int i = 0; i < 8; i++) {
                unsigned long long a2 = packf2(a[i]);
                fma2(acc2[i][0], a2, b2[0]);
                fma2(acc2[i][1], a2, b2[1]);
                fma2(acc2[i][2], a2, b2[2]);
                fma2(acc2[i][3], a2, b2[3]);
            }
        }
        if (more) {
            int nb = buf ^ 1;
#pragma unroll
            for (int q = 0; q < 4; q++) {
                As[nb][q * 4 + 0][tid] = ((float*)&rA[q])[0];
                As[nb][q * 4 + 1][tid] = ((float*)&rA[q])[1];
                As[nb][q * 4 + 2][tid] = ((float*)&rA[q])[2];
                As[nb][q * 4 + 3][tid] = ((float*)&rA[q])[3];
            }
            *(float4*)&Bs[nb][brow][bc] = rB0;
            *(float4*)&Bs[nb][brow][bc + 4] = rB1;
        }
        __syncthreads();
    }

    float asv[8], adv[8];
#pragma unroll
    for (int j = 0; j < 8; j++) {
        asv[j] = att_src[tx * 8 + j];
        adv[j] = att_dst[tx * 8 + j];
    }
#pragma unroll
    for (int i = 0; i < 8; i++) {
        int r = row0 + ty * 8 + i;
        if (r < M) {
            const float* accf = (const float*)&acc2[i][0];
            *(float4*)&C[(size_t)r * N + tx * 8] = *(const float4*)&accf[0];
            *(float4*)&C[(size_t)r * N + tx * 8 + 4] = *(const float4*)&accf[4];
            float as = 0.f, ad = 0.f;
#pragma unroll
            for (int j = 0; j < 8; j++) {
                as += accf[j] * asv[j];
                ad += accf[j] * adv[j];
            }
            g_asrc1[r * 8 + tx] = as;
            g_adst1[r * 8 + tx] = ad;
        }
    }
}

// ---------------- CSR build ----------------
__global__ void hist_dst(const int* __restrict__ ei, int E) {
    int e = blockIdx.x * blockDim.x + threadIdx.x;
    if (e < E) atomicAdd(&g_deg[ei[E + e]], 1);
}

__global__ void scan_local(int Nn) {
    __shared__ int wsum[32];
    int i = blockIdx.x * 1024 + threadIdx.x;
    int lane = threadIdx.x & 31, wid = threadIdx.x >> 5;
    int v = (i < Nn) ? g_deg[i] : 0;
    int sc = v;
#pragma unroll
    for (int o = 1; o < 32; o <<= 1) {
        int t = __shfl_up_sync(~0u, sc, o);
        if (lane >= o) sc += t;
    }
    if (lane == 31) wsum[wid] = sc;
    __syncthreads();
    if (wid == 0) {
        int ws = wsum[lane];
#pragma unroll
        for (int o = 1; o < 32; o <<= 1) {
            int t = __shfl_up_sync(~0u, ws, o);
            if (lane >= o) ws += t;
        }
        wsum[lane] = ws;
    }
    __syncthreads();
    int excl = sc - v + (wid > 0 ? wsum[wid - 1] : 0);
    if (i < Nn) g_start[i] = excl;
    if (threadIdx.x == 1023) g_bsum[blockIdx.x] = excl + v;
}

__global__ void scan_spine(int nb, int Nn) {
    int lane = threadIdx.x;
    int v0 = (lane * 2 < nb) ? g_bsum[lane * 2] : 0;
    int v1 = (lane * 2 + 1 < nb) ? g_bsum[lane * 2 + 1] : 0;
    int s = v0 + v1;
    int sc = s;
#pragma unroll
    for (int o = 1; o < 32; o <<= 1) {
        int t = __shfl_up_sync(~0u, sc, o);
        if (lane >= o) sc += t;
    }
    int excl = sc - s;
    if (lane * 2 < nb) g_bsum[lane * 2] = excl;
    if (lane * 2 + 1 < nb) g_bsum[lane * 2 + 1] = excl + v0;
    if (lane == 31) g_start[Nn] = sc;
}

__global__ void scan_add(int Nn) {
    int i = blockIdx.x * blockDim.x + threadIdx.x;
    if (i >= Nn) return;
    int s = g_start[i] + g_bsum[i >> 10];
    g_start[i] = s;
    g_cursor[i] = s;
}

__global__ void scatter_csr(const int* __restrict__ ei, int E) {
    int e = blockIdx.x * blockDim.x + threadIdx.x;
    if (e >= E) return;
    int d = ei[E + e];
    int pos = atomicAdd(&g_cursor[d], 1);
    g_csrc[pos] = ei[e];
}

// ---------------- layer-2 attention logits ----------------
__global__ void node_attn2(const float* __restrict__ att_src, const float* __restrict__ att_dst, int Nn) {
    int i = blockIdx.x * blockDim.x + threadIdx.x;
    if (i >= Nn) return;
    const float* h = &g_h2[i * 40];
    float as = 0.f, ad = 0.f;
#pragma unroll
    for (int c = 0; c < 40; c++) {
        float v = h[c];
        as += v * att_src[c];
        ad += v * att_dst[c];
    }
    g_as2[i] = as;
    g_ad2[i] = ad;
}

// ---------------- SGEMM2 (64x64x16 tiles) ----------------
__global__ void sgemm64(const float* __restrict__ A, const float* __restrict__ B,
                        float* __restrict__ C, int M, int N, int K) {
    __shared__ float As[16][64];
    __shared__ float Bs[16][64];
    int tid = threadIdx.x;
    int tx = tid & 15, ty = tid >> 4;
    int row0 = blockIdx.x * 64;

    int arow = tid >> 2, ak = (tid & 3) << 2;
    int brow = tid >> 4, bc = (tid & 15) << 2;

    float acc[4][4] = {};

    for (int k0 = 0; k0 < K; k0 += 16) {
        float4 av = make_float4(0.f, 0.f, 0.f, 0.f);
        if (row0 + arow < M)
            av = *(const float4*)&A[(size_t)(row0 + arow) * K + k0 + ak];
        As[ak + 0][arow] = av.x;
        As[ak + 1][arow] = av.y;
        As[ak + 2][arow] = av.z;
        As[ak + 3][arow] = av.w;

        float4 bv = make_float4(0.f, 0.f, 0.f, 0.f);
        if (bc < N)
            bv = *(const float4*)&B[(size_t)(k0 + brow) * N + bc];
        *(float4*)&Bs[brow][bc] = bv;

        __syncthreads();
#pragma unroll
        for (int kk = 0; kk < 16; kk++) {
            float a0 = As[kk][ty * 4 + 0];
            float a1 = As[kk][ty * 4 + 1];
            float a2 = As[kk][ty * 4 + 2];
            float a3 = As[kk][ty * 4 + 3];
            float4 b = *(float4*)&Bs[kk][tx * 4];
            acc[0][0] += a0 * b.x; acc[0][1] += a0 * b.y; acc[0][2] += a0 * b.z; acc[0][3] += a0 * b.w;
            acc[1][0] += a1 * b.x; acc[1][1] += a1 * b.y; acc[1][2] += a1 * b.z; acc[1][3] += a1 * b.w;
            acc[2][0] += a2 * b.x; acc[2][1] += a2 * b.y; acc[2][2] += a2 * b.z; acc[2][3] += a2 * b.w;
            acc[3][0] += a3 * b.x; acc[3][1] += a3 * b.y; acc[3][2] += a3 * b.z; acc[3][3] += a3 * b.w;
        }
        __syncthreads();
    }
#pragma unroll
    for (int i = 0; i < 4; i++) {
        int r = row0 + ty * 4 + i;
        if (r >= M) continue;
#pragma unroll
        for (int j = 0; j < 4; j++) {
            int c = tx * 4 + j;
            if (c < N) C[(size_t)r * N + c] = acc[i][j];
        }
    }
}

// ---------------- Layer 1 aggregation: warp per node ----------------
__global__ void __launch_bounds__(256) agg1(const float* __restrict__ b1, int Nn) {
    int gw = (blockIdx.x * blockDim.x + threadIdx.x) >> 5;
    if (gw >= Nn) return;
    int i = gw;
    int lane = threadIdx.x & 31;
    int h = lane >> 2;
    const float2* h1f2 = (const float2*)g_h1;

    float adst_w = g_adst1[i * 8 + (lane & 7)];
    float wself = __expf(leaky(g_asrc1[i * 8 + h] + g_adst1[i * 8 + h]));
    float denom = wself;
    float2 hv0 = h1f2[i * 32 + lane];
    float2 acc = make_float2(wself * hv0.x, wself * hv0.y);

    int st = g_start[i], en = g_start[i + 1];
    for (int e0 = st; e0 < en; e0 += 4) {
        int idx = e0 + (lane >> 3);
        bool valid = idx < en;
        int s = valid ? g_csrc[idx] : 0;
        float w = valid ? __expf(leaky(g_asrc1[s * 8 + (lane & 7)] + adst_w)) : 0.f;
#pragma unroll
        for (int j = 0; j < 4; j++) {
            int sj = __shfl_sync(~0u, s, j * 8);
            float wj = __shfl_sync(~0u, w, j * 8 + h);
            float2 hv = h1f2[sj * 32 + lane];
            acc.x += wj * hv.x;
            acc.y += wj * hv.y;
            denom += wj;
        }
    }
    float inv = 1.f / (denom + 1e-16f);
    float2 bb = ((const float2*)b1)[lane];
    float vx = acc.x * inv + bb.x;
    float vy = acc.y * inv + bb.y;
    ((float2*)g_h2in)[i * 32 + lane] = make_float2(vx > 0.f ? vx : 0.f, vy > 0.f ? vy : 0.f);
}

// ---------------- Layer 2 aggregation: warp per node ----------------
__global__ void __launch_bounds__(256) agg2(const float* __restrict__ b2,
                                            float* __restrict__ out, int Nn) {
    int gw = (blockIdx.x * blockDim.x + threadIdx.x) >> 5;
    if (gw >= Nn) return;
    int i = gw;
    int lane = threadIdx.x & 31;
    int cl = lane < 20 ? lane : 0;
    const float2* h2f2 = (const float2*)g_h2;

    float ad = g_ad2[i];
    float wself = __expf(leaky(g_as2[i] + ad));
    float denom = wself;
    float2 hv0 = h2f2[i * 20 + cl];
    float2 acc = make_float2(wself * hv0.x, wself * hv0.y);

    int st = g_start[i], en = g_start[i + 1];
    for (int e0 = st; e0 < en; e0 += 32) {
        int idx = e0 + lane;
        bool valid = idx < en;
        int s = valid ? g_csrc[idx] : 0;
        float w = valid ? __expf(leaky(g_as2[s] + ad)) : 0.f;
        int nleft = en - e0;
        int cnt = nleft < 32 ? nleft : 32;
#pragma unroll 8
        for (int j = 0; j < cnt; j++) {
            int sj = __shfl_sync(~0u, s, j);
            float wj = __shfl_sync(~0u, w, j);
            float2 hv = h2f2[sj * 20 + cl];
            acc.x += wj * hv.x;
            acc.y += wj * hv.y;
            denom += wj;
        }
    }
    float inv = 1.f / (denom + 1e-16f);
    float2 bb = ((const float2*)b2)[cl];
    float vx = acc.x * inv + bb.x;
    float vy = acc.y * inv + bb.y;

    float mloc = (lane < 20) ? fmaxf(vx, vy) : -1e30f;
#pragma unroll
    for (int o = 16; o > 0; o >>= 1) mloc = fmaxf(mloc, __shfl_xor_sync(~0u, mloc, o));
    float sloc = (lane < 20) ? (__expf(vx - mloc) + __expf(vy - mloc)) : 0.f;
#pragma unroll
    for (int o = 16; o > 0; o >>= 1) sloc += __shfl_xor_sync(~0u, sloc, o);
    float lse = mloc + logf(sloc);
    if (lane < 20)
        ((float2*)out)[i * 20 + lane] = make_float2(vx - lse, vy - lse);
}

// ---------------- launch: fork CSR chain onto side stream, join before agg1 ----------------
extern "C" void kernel_launch(void* const* d_in, const int* in_sizes, int n_in,
                              void* d_out, int out_size) {
    const float* x   = (const float*)d_in[0];
    const int*   ei  = (const int*)d_in[1];
    const float* W1  = (const float*)d_in[2];
    const float* as1 = (const float*)d_in[3];
    const float* ad1 = (const float*)d_in[4];
    const float* b1  = (const float*)d_in[5];
    const float* W2  = (const float*)d_in[6];
    const float* as2 = (const float*)d_in[7];
    const float* ad2 = (const float*)d_in[8];
    const float* b2  = (const float*)d_in[9];
    float* out = (float*)d_out;

    int Nn = in_sizes[0] / 512;   // 50000
    int E  = in_sizes[1] / 2;     // 1600000

    void *ph1, *ph2in, *ph2, *pdeg;
    cudaGetSymbolAddress(&ph1, g_h1);
    cudaGetSymbolAddress(&ph2in, g_h2in);
    cudaGetSymbolAddress(&ph2, g_h2);
    cudaGetSymbolAddress(&pdeg, g_deg);

    const int T = 256;
    int nChunks = (Nn + 1023) / 1024;
    int aggBlocks = (Nn + 7) / 8;

    // fork-join: CSR chain on side stream, sgemm1k on main stream.
    // Handles are created per call and intentionally leaked (host code runs only
    // on the correctness + capture calls; destroying mid-capture is unsafe).
    cudaStream_t s1;
    cudaStreamCreateWithFlags(&s1, cudaStreamNonBlocking);
    cudaEvent_t evFork, evJoin;
    cudaEventCreateWithFlags(&evFork, cudaEventDisableTiming);
    cudaEventCreateWithFlags(&evJoin, cudaEventDisableTiming);

    cudaEventRecord(evFork, 0);
    cudaStreamWaitEvent(s1, evFork, 0);

    // side stream: CSR build
    cudaMemsetAsync(pdeg, 0, (size_t)Nn * sizeof(int), s1);
    hist_dst<<<(E + T - 1) / T, T, 0, s1>>>(ei, E);
    scan_local<<<nChunks, 1024, 0, s1>>>(Nn);
    scan_spine<<<1, 32, 0, s1>>>(nChunks, Nn);
    scan_add<<<(Nn + T - 1) / T, T, 0, s1>>>(Nn);
    scatter_csr<<<(E + T - 1) / T, T, 0, s1>>>(ei, E);
    cudaEventRecord(evJoin, s1);

    // main stream: layer-1 GEMM (+ fused attn logits), concurrent with CSR build
    sgemm1k<<<(Nn + 127) / 128, 128>>>(x, W1, (float*)ph1, as1, ad1, Nn);

    // join: agg1 needs both CSR and h1
    cudaStreamWaitEvent(0, evJoin, 0);
    agg1<<<aggBlocks, T>>>(b1, Nn);

    // layer 2
    sgemm64<<<(Nn + 63) / 64, T>>>((const float*)ph2in, W2, (float*)ph2, Nn, 40, 64);
    node_attn2<<<(Nn + T - 1) / T, T>>>(as2, ad2, Nn);
    agg2<<<aggBlocks, T>>>(b2, out, Nn);
}

// round 13
// speedup vs baseline: 1.3829x; 1.0613x over previous
#include <cuda_runtime.h>
#include <cuda_bf16.h>

#define NMAX 50000
#define EMAX 1700000

// ---------------- scratch ----------------
__device__ float g_h1[NMAX * 64];
__device__ float g_asrc1[NMAX * 8];
__device__ float g_adst1[NMAX * 8];
__device__ float g_h2in[NMAX * 64];
__device__ float g_h2[NMAX * 40];
__device__ float g_as2[NMAX];
__device__ float g_ad2[NMAX];
// CSR
__device__ int g_deg[NMAX];
__device__ int g_start[NMAX + 1];
__device__ int g_cursor[NMAX];
__device__ int g_csrc[EMAX];
__device__ int g_bsum[64];

__device__ __forceinline__ float leaky(float e) { return e >= 0.f ? e : 0.2f * e; }

// packed f32x2 helpers
__device__ __forceinline__ unsigned long long packf2(float a) {
    unsigned long long r;
    asm("mov.b64 %0, {%1, %1};" : "=l"(r) : "f"(a));
    return r;
}
__device__ __forceinline__ void fma2(unsigned long long& d, unsigned long long a, unsigned long long b) {
    asm("fma.rn.f32x2 %0, %1, %2, %3;" : "=l"(d) : "l"(a), "l"(b), "l"(d));
}

// ---------------- SGEMM1: C[M,64] = A[M,512] @ B[512,64] + fused attn logits ----------------
__global__ void __launch_bounds__(128) sgemm1k(const float* __restrict__ A,
                                               const float* __restrict__ B,
                                               float* __restrict__ C,
                                               const float* __restrict__ att_src,
                                               const float* __restrict__ att_dst,
                                               int M) {
    const int K = 512, N = 64;
    __shared__ float As[2][16][128];
    __shared__ float Bs[2][16][64];
    int tid = threadIdx.x;
    int tx = tid & 7, ty = tid >> 3;
    int row0 = blockIdx.x * 128;

    int aRowG = row0 + tid;
    if (aRowG >= M) aRowG = M - 1;
    const float* Arow = A + (size_t)aRowG * K;

    int brow = tid >> 3, bc = (tid & 7) * 8;

    unsigned long long acc2[8][4] = {};
    float4 rA[4], rB0, rB1;

    {
        rA[0] = *(const float4*)&Arow[0];
        rA[1] = *(const float4*)&Arow[4];
        rA[2] = *(const float4*)&Arow[8];
        rA[3] = *(const float4*)&Arow[12];
        rB0 = *(const float4*)&B[(size_t)brow * N + bc];
        rB1 = *(const float4*)&B[(size_t)brow * N + bc + 4];
#pragma unroll
        for (int q = 0; q < 4; q++) {
            As[0][q * 4 + 0][tid] = ((float*)&rA[q])[0];
            As[0][q * 4 + 1][tid] = ((float*)&rA[q])[1];
            As[0][q * 4 + 2][tid] = ((float*)&rA[q])[2];
            As[0][q * 4 + 3][tid] = ((float*)&rA[q])[3];
        }
        *(float4*)&Bs[0][brow][bc] = rB0;
        *(float4*)&Bs[0][brow][bc + 4] = rB1;
    }
    __syncthreads();

    int buf = 0;
    for (int k0 = 0; k0 < K; k0 += 16, buf ^= 1) {
        bool more = (k0 + 16 < K);
        if (more) {
            rA[0] = *(const float4*)&Arow[k0 + 16];
            rA[1] = *(const float4*)&Arow[k0 + 20];
            rA[2] = *(const float4*)&Arow[k0 + 24];
            rA[3] = *(const float4*)&Arow[k0 + 28];
            rB0 = *(const float4*)&B[(size_t)(k0 + 16 + brow) * N + bc];
            rB1 = *(const float4*)&B[(size_t)(k0 + 16 + brow) * N + bc + 4];
        }
#pragma unroll
        for (int kk = 0; kk < 16; kk++) {
            float a[8];
            *(float4*)&a[0] = *(float4*)&As[buf][kk][ty * 8];
            *(float4*)&a[4] = *(float4*)&As[buf][kk][ty * 8 + 4];
            unsigned long long b2[4];
            *(ulonglong2*)&b2[0] = *(ulonglong2*)&Bs[buf][kk][tx * 8];
            *(ulonglong2*)&b2[2] = *(ulonglong2*)&Bs[buf][kk][tx * 8 + 4];
#pragma unroll
            for (int i = 0; i < 8; i++) {
                unsigned long long a2 = packf2(a[i]);
                fma2(acc2[i][0], a2, b2[0]);
                fma2(acc2[i][1], a2, b2[1]);
                fma2(acc2[i][2], a2, b2[2]);
                fma2(acc2[i][3], a2, b2[3]);
            }
        }
        if (more) {
            int nb = buf ^ 1;
#pragma unroll
            for (int q = 0; q < 4; q++) {
                As[nb][q * 4 + 0][tid] = ((float*)&rA[q])[0];
                As[nb][q * 4 + 1][tid] = ((float*)&rA[q])[1];
                As[nb][q * 4 + 2][tid] = ((float*)&rA[q])[2];
                As[nb][q * 4 + 3][tid] = ((float*)&rA[q])[3];
            }
            *(float4*)&Bs[nb][brow][bc] = rB0;
            *(float4*)&Bs[nb][brow][bc + 4] = rB1;
        }
        __syncthreads();
    }

    float asv[8], adv[8];
#pragma unroll
    for (int j = 0; j < 8; j++) {
        asv[j] = att_src[tx * 8 + j];
        adv[j] = att_dst[tx * 8 + j];
    }
#pragma unroll
    for (int i = 0; i < 8; i++) {
        int r = row0 + ty * 8 + i;
        if (r < M) {
            const float* accf = (const float*)&acc2[i][0];
            *(float4*)&C[(size_t)r * N + tx * 8] = *(const float4*)&accf[0];
            *(float4*)&C[(size_t)r * N + tx * 8 + 4] = *(const float4*)&accf[4];
            float as = 0.f, ad = 0.f;
#pragma unroll
            for (int j = 0; j < 8; j++) {
                as += accf[j] * asv[j];
                ad += accf[j] * adv[j];
            }
            g_asrc1[r * 8 + tx] = as;
            g_adst1[r * 8 + tx] = ad;
        }
    }
}

// ---------------- CSR build ----------------
__global__ void hist_dst(const int* __restrict__ ei, int E) {
    int e = blockIdx.x * blockDim.x + threadIdx.x;
    if (e < E) atomicAdd(&g_deg[ei[E + e]], 1);
}

__global__ void scan_local(int Nn) {
    __shared__ int wsum[32];
    int i = blockIdx.x * 1024 + threadIdx.x;
    int lane = threadIdx.x & 31, wid = threadIdx.x >> 5;
    int v = (i < Nn) ? g_deg[i] : 0;
    int sc = v;
#pragma unroll
    for (int o = 1; o < 32; o <<= 1) {
        int t = __shfl_up_sync(~0u, sc, o);
        if (lane >= o) sc += t;
    }
    if (lane == 31) wsum[wid] = sc;
    __syncthreads();
    if (wid == 0) {
        int ws = wsum[lane];
#pragma unroll
        for (int o = 1; o < 32; o <<= 1) {
            int t = __shfl_up_sync(~0u, ws, o);
            if (lane >= o) ws += t;
        }
        wsum[lane] = ws;
    }
    __syncthreads();
    int excl = sc - v + (wid > 0 ? wsum[wid - 1] : 0);
    if (i < Nn) g_start[i] = excl;
    if (threadIdx.x == 1023) g_bsum[blockIdx.x] = excl + v;
}

__global__ void scan_spine(int nb, int Nn) {
    int lane = threadIdx.x;
    int v0 = (lane * 2 < nb) ? g_bsum[lane * 2] : 0;
    int v1 = (lane * 2 + 1 < nb) ? g_bsum[lane * 2 + 1] : 0;
    int s = v0 + v1;
    int sc = s;
#pragma unroll
    for (int o = 1; o < 32; o <<= 1) {
        int t = __shfl_up_sync(~0u, sc, o);
        if (lane >= o) sc += t;
    }
    int excl = sc - s;
    if (lane * 2 < nb) g_bsum[lane * 2] = excl;
    if (lane * 2 + 1 < nb) g_bsum[lane * 2 + 1] = excl + v0;
    if (lane == 31) g_start[Nn] = sc;
}

__global__ void scan_add(int Nn) {
    int i = blockIdx.x * blockDim.x + threadIdx.x;
    if (i >= Nn) return;
    int s = g_start[i] + g_bsum[i >> 10];
    g_start[i] = s;
    g_cursor[i] = s;
}

__global__ void scatter_csr(const int* __restrict__ ei, int E) {
    int e = blockIdx.x * blockDim.x + threadIdx.x;
    if (e >= E) return;
    int d = ei[E + e];
    int pos = atomicAdd(&g_cursor[d], 1);
    g_csrc[pos] = ei[e];
}

// ---------------- SGEMM2 (64x64x16 tiles) + attn2 logits via warp shfl ----------------
// blockBase allows launching row ranges: rows [blockBase*64, ...)
__global__ void sgemm2(const float* __restrict__ A, const float* __restrict__ B,
                       float* __restrict__ C,
                       const float* __restrict__ att_src, const float* __restrict__ att_dst,
                       int M, int N, int K, int blockBase) {
    __shared__ float As[16][64];
    __shared__ float Bs[16][64];
    int tid = threadIdx.x;
    int tx = tid & 15, ty = tid >> 4;
    int row0 = (blockBase + blockIdx.x) * 64;

    int arow = tid >> 2, ak = (tid & 3) << 2;
    int brow = tid >> 4, bc = (tid & 15) << 2;

    float acc[4][4] = {};

    for (int k0 = 0; k0 < K; k0 += 16) {
        float4 av = make_float4(0.f, 0.f, 0.f, 0.f);
        if (row0 + arow < M)
            av = *(const float4*)&A[(size_t)(row0 + arow) * K + k0 + ak];
        As[ak + 0][arow] = av.x;
        As[ak + 1][arow] = av.y;
        As[ak + 2][arow] = av.z;
        As[ak + 3][arow] = av.w;

        float4 bv = make_float4(0.f, 0.f, 0.f, 0.f);
        if (bc < N)
            bv = *(const float4*)&B[(size_t)(k0 + brow) * N + bc];
        *(float4*)&Bs[brow][bc] = bv;

        __syncthreads();
#pragma unroll
        for (int kk = 0; kk < 16; kk++) {
            float a0 = As[kk][ty * 4 + 0];
            float a1 = As[kk][ty * 4 + 1];
            float a2 = As[kk][ty * 4 + 2];
            float a3 = As[kk][ty * 4 + 3];
            float4 b = *(float4*)&Bs[kk][tx * 4];
            acc[0][0] += a0 * b.x; acc[0][1] += a0 * b.y; acc[0][2] += a0 * b.z; acc[0][3] += a0 * b.w;
            acc[1][0] += a1 * b.x; acc[1][1] += a1 * b.y; acc[1][2] += a1 * b.z; acc[1][3] += a1 * b.w;
            acc[2][0] += a2 * b.x; acc[2][1] += a2 * b.y; acc[2][2] += a2 * b.z; acc[2][3] += a2 * b.w;
            acc[3][0] += a3 * b.x; acc[3][1] += a3 * b.y; acc[3][2] += a3 * b.z; acc[3][3] += a3 * b.w;
        }
        __syncthreads();
    }

    // per-column attn vectors for this thread (cols tx*4..tx*4+3; zero beyond N)
    float asv[4] = {0.f, 0.f, 0.f, 0.f}, adv[4] = {0.f, 0.f, 0.f, 0.f};
#pragma unroll
    for (int j = 0; j < 4; j++) {
        int c = tx * 4 + j;
        if (c < N) { asv[j] = att_src[c]; adv[j] = att_dst[c]; }
    }

#pragma unroll
    for (int i = 0; i < 4; i++) {
        int r = row0 + ty * 4 + i;
        bool live = r < M;
        float pas = 0.f, pad = 0.f;
#pragma unroll
        for (int j = 0; j < 4; j++) {
            int c = tx * 4 + j;
            if (live && c < N) {
                C[(size_t)r * N + c] = acc[i][j];
                pas += acc[i][j] * asv[j];
                pad += acc[i][j] * adv[j];
            }
        }
        // reduce across the 16-lane tx group (warp = 2 such groups)
#pragma unroll
        for (int o = 8; o > 0; o >>= 1) {
            pas += __shfl_xor_sync(~0u, pas, o);
            pad += __shfl_xor_sync(~0u, pad, o);
        }
        if (live && tx == 0) {
            g_as2[r] = pas;
            g_ad2[r] = pad;
        }
    }
}

// ---------------- Layer 1 aggregation: warp per node, node-range ----------------
__global__ void __launch_bounds__(256) agg1(const float* __restrict__ b1, int base, int count) {
    int gw = (blockIdx.x * blockDim.x + threadIdx.x) >> 5;
    if (gw >= count) return;
    int i = base + gw;
    int lane = threadIdx.x & 31;
    int h = lane >> 2;
    const float2* h1f2 = (const float2*)g_h1;

    float adst_w = g_adst1[i * 8 + (lane & 7)];
    float wself = __expf(leaky(g_asrc1[i * 8 + h] + g_adst1[i * 8 + h]));
    float denom = wself;
    float2 hv0 = h1f2[i * 32 + lane];
    float2 acc = make_float2(wself * hv0.x, wself * hv0.y);

    int st = g_start[i], en = g_start[i + 1];
    for (int e0 = st; e0 < en; e0 += 4) {
        int idx = e0 + (lane >> 3);
        bool valid = idx < en;
        int s = valid ? g_csrc[idx] : 0;
        float w = valid ? __expf(leaky(g_asrc1[s * 8 + (lane & 7)] + adst_w)) : 0.f;
#pragma unroll
        for (int j = 0; j < 4; j++) {
            int sj = __shfl_sync(~0u, s, j * 8);
            float wj = __shfl_sync(~0u, w, j * 8 + h);
            float2 hv = h1f2[sj * 32 + lane];
            acc.x += wj * hv.x;
            acc.y += wj * hv.y;
            denom += wj;
        }
    }
    float inv = 1.f / (denom + 1e-16f);
    float2 bb = ((const float2*)b1)[lane];
    float vx = acc.x * inv + bb.x;
    float vy = acc.y * inv + bb.y;
    ((float2*)g_h2in)[i * 32 + lane] = make_float2(vx > 0.f ? vx : 0.f, vy > 0.f ? vy : 0.f);
}

// ---------------- Layer 2 aggregation: warp per node ----------------
__global__ void __launch_bounds__(256) agg2(const float* __restrict__ b2,
                                            float* __restrict__ out, int Nn) {
    int gw = (blockIdx.x * blockDim.x + threadIdx.x) >> 5;
    if (gw >= Nn) return;
    int i = gw;
    int lane = threadIdx.x & 31;
    int cl = lane < 20 ? lane : 0;
    const float2* h2f2 = (const float2*)g_h2;

    float ad = g_ad2[i];
    float wself = __expf(leaky(g_as2[i] + ad));
    float denom = wself;
    float2 hv0 = h2f2[i * 20 + cl];
    float2 acc = make_float2(wself * hv0.x, wself * hv0.y);

    int st = g_start[i], en = g_start[i + 1];
    for (int e0 = st; e0 < en; e0 += 32) {
        int idx = e0 + lane;
        bool valid = idx < en;
        int s = valid ? g_csrc[idx] : 0;
        float w = valid ? __expf(leaky(g_as2[s] + ad)) : 0.f;
        int nleft = en - e0;
        int cnt = nleft < 32 ? nleft : 32;
#pragma unroll 8
        for (int j = 0; j < cnt; j++) {
            int sj = __shfl_sync(~0u, s, j);
            float wj = __shfl_sync(~0u, w, j);
            float2 hv = h2f2[sj * 20 + cl];
            acc.x += wj * hv.x;
            acc.y += wj * hv.y;
            denom += wj;
        }
    }
    float inv = 1.f / (denom + 1e-16f);
    float2 bb = ((const float2*)b2)[cl];
    float vx = acc.x * inv + bb.x;
    float vy = acc.y * inv + bb.y;

    float mloc = (lane < 20) ? fmaxf(vx, vy) : -1e30f;
#pragma unroll
    for (int o = 16; o > 0; o >>= 1) mloc = fmaxf(mloc, __shfl_xor_sync(~0u, mloc, o));
    float sloc = (lane < 20) ? (__expf(vx - mloc) + __expf(vy - mloc)) : 0.f;
#pragma unroll
    for (int o = 16; o > 0; o >>= 1) sloc += __shfl_xor_sync(~0u, sloc, o);
    float lse = mloc + logf(sloc);
    if (lane < 20)
        ((float2*)out)[i * 20 + lane] = make_float2(vx - lse, vy - lse);
}

// ---------------- launch ----------------
extern "C" void kernel_launch(void* const* d_in, const int* in_sizes, int n_in,
                              void* d_out, int out_size) {
    const float* x   = (const float*)d_in[0];
    const int*   ei  = (const int*)d_in[1];
    const float* W1  = (const float*)d_in[2];
    const float* as1 = (const float*)d_in[3];
    const float* ad1 = (const float*)d_in[4];
    const float* b1  = (const float*)d_in[5];
    const float* W2  = (const float*)d_in[6];
    const float* as2 = (const float*)d_in[7];
    const float* ad2 = (const float*)d_in[8];
    const float* b2  = (const float*)d_in[9];
    float* out = (float*)d_out;

    int Nn = in_sizes[0] / 512;   // 50000
    int E  = in_sizes[1] / 2;     // 1600000

    void *ph1, *ph2in, *ph2, *pdeg;
    cudaGetSymbolAddress(&ph1, g_h1);
    cudaGetSymbolAddress(&ph2in, g_h2in);
    cudaGetSymbolAddress(&ph2, g_h2);
    cudaGetSymbolAddress(&pdeg, g_deg);

    const int T = 256;
    int nChunks = (Nn + 1023) / 1024;

    // tail split: nodes [0, nodesA) / [nodesA, Nn); gemm2 block split to match
    int totalBlocks2 = (Nn + 63) / 64;          // 782
    int gA2 = totalBlocks2 / 2;                 // 391
    int nodesA = gA2 * 64;                      // 25024
    int nodesB = Nn - nodesA;
    int aggBlocksA = (nodesA + 7) / 8;
    int aggBlocksB = (nodesB + 7) / 8;

    // streams/events created per call; intentionally leaked (host code runs only
    // on correctness + capture calls; destroying mid-capture is unsafe)
    cudaStream_t s1;
    cudaStreamCreateWithFlags(&s1, cudaStreamNonBlocking);
    cudaEvent_t evFork, evJoin, evA, evB;
    cudaEventCreateWithFlags(&evFork, cudaEventDisableTiming);
    cudaEventCreateWithFlags(&evJoin, cudaEventDisableTiming);
    cudaEventCreateWithFlags(&evA, cudaEventDisableTiming);
    cudaEventCreateWithFlags(&evB, cudaEventDisableTiming);

    // ---- fork 1: CSR build (s1) || sgemm1k (main) ----
    cudaEventRecord(evFork, 0);
    cudaStreamWaitEvent(s1, evFork, 0);

    cudaMemsetAsync(pdeg, 0, (size_t)Nn * sizeof(int), s1);
    hist_dst<<<(E + T - 1) / T, T, 0, s1>>>(ei, E);
    scan_local<<<nChunks, 1024, 0, s1>>>(Nn);
    scan_spine<<<1, 32, 0, s1>>>(nChunks, Nn);
    scan_add<<<(Nn + T - 1) / T, T, 0, s1>>>(Nn);
    scatter_csr<<<(E + T - 1) / T, T, 0, s1>>>(ei, E);
    cudaEventRecord(evJoin, s1);

    sgemm1k<<<(Nn + 127) / 128, 128>>>(x, W1, (float*)ph1, as1, ad1, Nn);
    cudaStreamWaitEvent(0, evJoin, 0);

    // ---- fork 2: agg1_a -> [sgemm2_a on s1 || agg1_b on main] ----
    agg1<<<aggBlocksA, T>>>(b1, 0, nodesA);
    cudaEventRecord(evA, 0);
    cudaStreamWaitEvent(s1, evA, 0);
    sgemm2<<<gA2, T, 0, s1>>>((const float*)ph2in, W2, (float*)ph2, as2, ad2, Nn, 40, 64, 0);
    cudaEventRecord(evB, s1);

    agg1<<<aggBlocksB, T>>>(b1, nodesA, nodesB);
    sgemm2<<<totalBlocks2 - gA2, T>>>((const float*)ph2in, W2, (float*)ph2, as2, ad2, Nn, 40, 64, gA2);

    // join: agg2 needs full h2/as2/ad2
    cudaStreamWaitEvent(0, evB, 0);
    agg2<<<(Nn + 7) / 8, T>>>(b2, out, Nn);
}